// round 3
// baseline (speedup 1.0000x reference)
#include <cuda_runtime.h>

#define NN 4096
#define FF 16
#define CM 512                   // X rows staged per chunk (32 KB smem)
#define THREADS 256
#define WARPS_PER_BLOCK 8
#define R 2                      // output rows per warp
#define ROWS_PER_BLOCK (WARPS_PER_BLOCK * R)   // 16
#define ITERS_TOTAL (NN / 32)                  // 128 warp-iterations over m
#define ITERS_PER_CHUNK (CM / 32)              // 16

// 12 independent scalar loads (one per stream), fully coalesced per warp
#define LOAD12(buf, gm_)                                              \
    buf[0] = pW0[gm_]; buf[1]  = pW0[NN2 + gm_]; buf[2]  = pW0[2 * NN2 + gm_]; \
    buf[3] = pT0[gm_]; buf[4]  = pT0[NN2 + gm_]; buf[5]  = pT0[2 * NN2 + gm_]; \
    buf[6] = pW1[gm_]; buf[7]  = pW1[NN2 + gm_]; buf[8]  = pW1[2 * NN2 + gm_]; \
    buf[9] = pT1[gm_]; buf[10] = pT1[NN2 + gm_]; buf[11] = pT1[2 * NN2 + gm_];

__global__ void __launch_bounds__(THREADS, 2)
diffusion_conv_kernel(const float* __restrict__ X,
                      const float* __restrict__ theta,
                      const float* __restrict__ Wp,
                      const float* __restrict__ WTp,
                      float* __restrict__ out)
{
    // XOR-swizzled X chunk: float4 slot for (row ml, feature-group g) at
    // ml*4 + (g ^ ((ml>>1)&3)) — conflict-free STS.128 and LDS.128.
    __shared__ __align__(16) float4 Xs4[CM * 4];

    const int tid  = threadIdx.x;
    const int warp = tid >> 5;
    const int lane = tid & 31;

    const int n0 = blockIdx.x * ROWS_PER_BLOCK + warp * R;
    const size_t NN2 = (size_t)NN * NN;

    const float ta0 = theta[0], tb0 = theta[1];
    const float ta1 = theta[2], tb1 = theta[3];
    const float ta2 = theta[4], tb2 = theta[5];

    const float* pW0 = Wp  + (size_t)n0 * NN;
    const float* pT0 = WTp + (size_t)n0 * NN;
    const float* pW1 = pW0 + NN;
    const float* pT1 = pT0 + NN;

    float acc0[FF], acc1[FF];
#pragma unroll
    for (int f = 0; f < FF; f++) { acc0[f] = 0.0f; acc1[f] = 0.0f; }

    // prime the pipeline: loads for iteration 0
    float cur[12];
    {
        const size_t gm = (size_t)lane;
        LOAD12(cur, gm)
    }

#pragma unroll 1
    for (int it = 0; it < ITERS_TOTAL; it++) {
        // chunk boundary: stage X[c0 : c0+CM]. Prefetched gmem loads (issued
        // last iteration) stay in flight through the barrier.
        if ((it & (ITERS_PER_CHUNK - 1)) == 0) {
            const int c0 = (it / ITERS_PER_CHUNK) * CM;
            __syncthreads();
#pragma unroll
            for (int i = tid; i < CM; i += THREADS) {
                const float4* xr = (const float4*)(X + (size_t)(c0 + i) * FF);
                const int s = (i >> 1) & 3;
                float4 a = xr[0], b = xr[1], c = xr[2], d = xr[3];
                Xs4[i * 4 + (0 ^ s)] = a;
                Xs4[i * 4 + (1 ^ s)] = b;
                Xs4[i * 4 + (2 ^ s)] = c;
                Xs4[i * 4 + (3 ^ s)] = d;
            }
            __syncthreads();
        }

        // prefetch next iteration's 12 loads (keeps ~24 LDGs in flight)
        float nxt[12];
        if (it + 1 < ITERS_TOTAL) {
            const size_t gmn = (size_t)((it + 1) * 32 + lane);
            LOAD12(nxt, gmn)
        }

        // combine current bundle into M row-scalars
        const float m0 = ta0 * cur[0] + ta1 * cur[1] + ta2 * cur[2]
                       + tb0 * cur[3] + tb1 * cur[4] + tb2 * cur[5];
        const float m1 = ta0 * cur[6] + ta1 * cur[7] + ta2 * cur[8]
                       + tb0 * cur[9] + tb1 * cur[10] + tb2 * cur[11];

        // multiply against X row ml from smem
        const int ml = (it & (ITERS_PER_CHUNK - 1)) * 32 + lane;
        const int sbase = ml * 4;
        const int s = (ml >> 1) & 3;
#pragma unroll
        for (int g = 0; g < 4; g++) {
            float4 xs = Xs4[sbase + (g ^ s)];
            acc0[4 * g + 0] += m0 * xs.x;  acc1[4 * g + 0] += m1 * xs.x;
            acc0[4 * g + 1] += m0 * xs.y;  acc1[4 * g + 1] += m1 * xs.y;
            acc0[4 * g + 2] += m0 * xs.z;  acc1[4 * g + 2] += m1 * xs.z;
            acc0[4 * g + 3] += m0 * xs.w;  acc1[4 * g + 3] += m1 * xs.w;
        }

#pragma unroll
        for (int j = 0; j < 12; j++) cur[j] = nxt[j];
    }

    // cross-lane reduction
#pragma unroll
    for (int f = 0; f < FF; f++) {
#pragma unroll
        for (int d = 16; d >= 1; d >>= 1) {
            acc0[f] += __shfl_xor_sync(0xFFFFFFFFu, acc0[f], d);
            acc1[f] += __shfl_xor_sync(0xFFFFFFFFu, acc1[f], d);
        }
    }

    if (lane == 0) {
        const float* x0 = X + (size_t)n0 * FF;
        float* o0 = out + (size_t)n0 * FF;
#pragma unroll
        for (int f = 0; f < FF; f++) {
            o0[f]      = x0[f]      + acc0[f];
            o0[FF + f] = x0[FF + f] + acc1[f];
        }
    }
}

extern "C" void kernel_launch(void* const* d_in, const int* in_sizes, int n_in,
                              void* d_out, int out_size)
{
    const float* X     = (const float*)d_in[0];   // [4096, 16]
    const float* theta = (const float*)d_in[1];   // [3, 2]
    const float* Wp    = (const float*)d_in[2];   // [3, 4096, 4096]
    const float* WTp   = (const float*)d_in[3];   // [3, 4096, 4096]
    float* out = (float*)d_out;                   // [4096, 16]

    dim3 grid(NN / ROWS_PER_BLOCK);               // 256 blocks
    dim3 block(THREADS);
    diffusion_conv_kernel<<<grid, block>>>(X, theta, Wp, WTp, out);
}